// round 6
// baseline (speedup 1.0000x reference)
#include <cuda_runtime.h>

// QLSTM collapsed analytically:
//   quantum_gate(comb, p)[:, k] = prod_{j<=k} cos(p_j) * cos(comb_j)
// Only k < H=4 used; comb[0:4] = x  => gates depend only on x_t.
// Per (b,k): c_t = f*c + i*g ; h = o*tanh(c); gate args in [-1,1], |c| <= 2.1.
//
// Mapping: warp = one batch element b; lane = time chunk (0..31) of 4 steps.
// Pass 1: per chunk compute & CACHE f, i*g, o (48 regs); accumulate (prod f, c0).
// Warp scan (5 rounds) composes 32 chunk affine maps -> cin per chunk.
// Pass 2: pure-register recurrence c=fma(f,c,ig), h=o*tanh(c). No reloads.

#define T_STEPS 128
#define BATCH   4096
#define CHUNK   4
#define NCHUNK  32
#define FULLMASK 0xffffffffu

// sigmoid(2u), |u|<=0.5 : 0.5 + u*q(u^2); tanh Taylor deg-9 halved, err ~2e-6
__device__ __forceinline__ float sig_poly(float u) {
    float w = u * u;
    float q = fmaf(w, fmaf(w, fmaf(w, fmaf(w, 0.010934744f,
                                              -0.026984127f),
                                       0.066666667f),
                               -0.166666667f),
                       0.5f);
    return fmaf(u, q, 0.5f);
}
// tanh Pade(5,4); |z|<=1, err ~4e-8
__device__ __forceinline__ float tanh_p54(float z) {
    float w = z * z;
    float n = z * fmaf(w, fmaf(w, 1.0f, 105.0f), 945.0f);
    float d =     fmaf(w, fmaf(w, 15.0f, 420.0f), 945.0f);
    return __fdividef(n, d);
}
// tanh Pade(7,6); |z|<=2.5, err ~1e-6
__device__ __forceinline__ float tanh_p76(float z) {
    float w = z * z;
    float n = z * fmaf(w, fmaf(w, 21.0f, 1260.0f), 10395.0f);
    float d =     fmaf(w, fmaf(w, fmaf(w, 1.0f, 210.0f), 4725.0f), 10395.0f);
    return __fdividef(n, d);
}

__global__ void __launch_bounds__(128, 5) qlstm_kernel(
    const float* __restrict__ inp,   // [T, B, 4]
    const float* __restrict__ prm_f, // [8]
    const float* __restrict__ prm_i,
    const float* __restrict__ prm_g,
    const float* __restrict__ prm_o,
    float* __restrict__ out)         // [T*B*4 + B*4 + B*4]
{
    const int gtid  = blockIdx.x * blockDim.x + threadIdx.x;
    const int b     = gtid >> 5;            // warp id = batch element
    const int lane  = threadIdx.x & 31;     // time chunk 0..31
    const int t0    = lane * CHUNK;

    // per-k parameter prefix products (uniform)
    float AFh[4], AIh[4], AG[4], AOh[4];
    {
        float pf_ = 1.0f, pi_ = 1.0f, pg_ = 1.0f, po_ = 1.0f;
#pragma unroll
        for (int j = 0; j < 4; ++j) {
            pf_ *= __cosf(prm_f[j]);
            pi_ *= __cosf(prm_i[j]);
            pg_ *= __cosf(prm_g[j]);
            po_ *= __cosf(prm_o[j]);
            AFh[j] = 0.5f * pf_;   // sigmoid poly takes arg/2
            AIh[j] = 0.5f * pi_;
            AG[j]  = pg_;
            AOh[j] = 0.5f * po_;
        }
    }

    const float4* __restrict__ xin = (const float4*)inp;

    // ---- pass 1: compute & cache gates, accumulate chunk affine map ----
    float Fc[CHUNK][4];   // forget gates
    float Gc[CHUNK][4];   // i*g
    float Oc[CHUNK][4];   // output gates
    float cl0 = 0.f, cl1 = 0.f, cl2 = 0.f, cl3 = 0.f;
    float pf0 = 1.f, pf1 = 1.f, pf2 = 1.f, pf3 = 1.f;

#pragma unroll
    for (int it = 0; it < CHUNK; ++it) {
        float4 x = xin[(t0 + it) * BATCH + b];
        float P0 = __cosf(x.x);
        float P1 = P0 * __cosf(x.y);
        float P2 = P1 * __cosf(x.z);
        float P3 = P2 * __cosf(x.w);

        float f, i, g, ig;
        f = sig_poly(AFh[0] * P0); i = sig_poly(AIh[0] * P0); g = tanh_p54(AG[0] * P0);
        ig = i * g; Fc[it][0] = f; Gc[it][0] = ig; Oc[it][0] = sig_poly(AOh[0] * P0);
        cl0 = fmaf(f, cl0, ig); pf0 *= f;

        f = sig_poly(AFh[1] * P1); i = sig_poly(AIh[1] * P1); g = tanh_p54(AG[1] * P1);
        ig = i * g; Fc[it][1] = f; Gc[it][1] = ig; Oc[it][1] = sig_poly(AOh[1] * P1);
        cl1 = fmaf(f, cl1, ig); pf1 *= f;

        f = sig_poly(AFh[2] * P2); i = sig_poly(AIh[2] * P2); g = tanh_p54(AG[2] * P2);
        ig = i * g; Fc[it][2] = f; Gc[it][2] = ig; Oc[it][2] = sig_poly(AOh[2] * P2);
        cl2 = fmaf(f, cl2, ig); pf2 *= f;

        f = sig_poly(AFh[3] * P3); i = sig_poly(AIh[3] * P3); g = tanh_p54(AG[3] * P3);
        ig = i * g; Fc[it][3] = f; Gc[it][3] = ig; Oc[it][3] = sig_poly(AOh[3] * P3);
        cl3 = fmaf(f, cl3, ig); pf3 *= f;
    }

    // ---- scan over 32 chunks: c_out = C + F*c_in ----
    float F0 = pf0, C0 = cl0, F1 = pf1, C1 = cl1;
    float F2 = pf2, C2 = cl2, F3 = pf3, C3 = cl3;
#pragma unroll
    for (int off = 1; off <= 16; off <<= 1) {
        float Fo0 = __shfl_up_sync(FULLMASK, F0, off), Co0 = __shfl_up_sync(FULLMASK, C0, off);
        float Fo1 = __shfl_up_sync(FULLMASK, F1, off), Co1 = __shfl_up_sync(FULLMASK, C1, off);
        float Fo2 = __shfl_up_sync(FULLMASK, F2, off), Co2 = __shfl_up_sync(FULLMASK, C2, off);
        float Fo3 = __shfl_up_sync(FULLMASK, F3, off), Co3 = __shfl_up_sync(FULLMASK, C3, off);
        if (lane >= off) {
            C0 = fmaf(F0, Co0, C0); F0 *= Fo0;
            C1 = fmaf(F1, Co1, C1); F1 *= Fo1;
            C2 = fmaf(F2, Co2, C2); F2 *= Fo2;
            C3 = fmaf(F3, Co3, C3); F3 *= Fo3;
        }
    }
    float c0 = __shfl_up_sync(FULLMASK, C0, 1);
    float c1 = __shfl_up_sync(FULLMASK, C1, 1);
    float c2 = __shfl_up_sync(FULLMASK, C2, 1);
    float c3 = __shfl_up_sync(FULLMASK, C3, 1);
    if (lane == 0) { c0 = 0.f; c1 = 0.f; c2 = 0.f; c3 = 0.f; }

    // ---- pass 2: pure-register recurrence, emit h ----
    float4* __restrict__ out4 = (float4*)out;
    float h0 = 0.f, h1 = 0.f, h2 = 0.f, h3 = 0.f;

#pragma unroll
    for (int it = 0; it < CHUNK; ++it) {
        c0 = fmaf(Fc[it][0], c0, Gc[it][0]);
        c1 = fmaf(Fc[it][1], c1, Gc[it][1]);
        c2 = fmaf(Fc[it][2], c2, Gc[it][2]);
        c3 = fmaf(Fc[it][3], c3, Gc[it][3]);

        h0 = Oc[it][0] * tanh_p76(c0);
        h1 = Oc[it][1] * tanh_p76(c1);
        h2 = Oc[it][2] * tanh_p76(c2);
        h3 = Oc[it][3] * tanh_p76(c3);

        __stcs(&out4[(t0 + it) * BATCH + b], make_float4(h0, h1, h2, h3));
    }

    if (lane == NCHUNK - 1) {
        out4[T_STEPS * BATCH + b]         = make_float4(h0, h1, h2, h3); // hx
        out4[T_STEPS * BATCH + BATCH + b] = make_float4(c0, c1, c2, c3); // cx
    }
}

extern "C" void kernel_launch(void* const* d_in, const int* in_sizes, int n_in,
                              void* d_out, int out_size) {
    (void)in_sizes; (void)n_in; (void)out_size;
    const float* inp   = (const float*)d_in[0];
    const float* prm_f = (const float*)d_in[1];
    const float* prm_i = (const float*)d_in[2];
    const float* prm_g = (const float*)d_in[3];
    const float* prm_o = (const float*)d_in[4];
    float* out = (float*)d_out;

    // 4096 warps (one per batch element), 4 warps per block -> 1024 blocks
    qlstm_kernel<<<1024, 128>>>(inp, prm_f, prm_i, prm_g, prm_o, out);
}

// round 7
// speedup vs baseline: 1.1603x; 1.1603x over previous
#include <cuda_runtime.h>

// QLSTM collapsed analytically:
//   quantum_gate(comb, p)[:, k] = prod_{j<=k} cos(p_j) * cos(comb_j)
// Only k < H=4 used; comb[0:4] = x  => gates depend only on x_t.
// Per (b,k): c = f*c + i*g ; h = o*tanh(c); gate args in [-1,1], |c| <= 2.1.
//
// Mapping: warp = 2 batch els x HALF of T (64 steps).
//   lane = (chunk 0..15)*2 + bsub(0..1); chunk = 4 steps. 4096 warps total.
// Pass 1: load x once, compute & cache f, i*g, o (48 regs); chunk affine aggs.
// Warp scan (4 rounds) over 16 chunks; halves linked via smem (c at t=63).
// Pass 2: pure-register recurrence + streaming stores. No reloads.

#define T_STEPS 128
#define BATCH   4096
#define CHUNK   4
#define FULLMASK 0xffffffffu

// sigmoid(2u), |u|<=0.5 : 0.5 + u*q(u^2); tanh Taylor deg-9 halved, err ~2e-6
__device__ __forceinline__ float sig_poly(float u) {
    float w = u * u;
    float q = fmaf(w, fmaf(w, fmaf(w, fmaf(w, 0.010934744f,
                                              -0.026984127f),
                                       0.066666667f),
                               -0.166666667f),
                       0.5f);
    return fmaf(u, q, 0.5f);
}
// tanh Pade(5,4); |z|<=1, err ~4e-8
__device__ __forceinline__ float tanh_p54(float z) {
    float w = z * z;
    float n = z * fmaf(w, fmaf(w, 1.0f, 105.0f), 945.0f);
    float d =     fmaf(w, fmaf(w, 15.0f, 420.0f), 945.0f);
    return __fdividef(n, d);
}
// tanh Pade(7,6); |z|<=2.5, err ~1e-6
__device__ __forceinline__ float tanh_p76(float z) {
    float w = z * z;
    float n = z * fmaf(w, fmaf(w, 21.0f, 1260.0f), 10395.0f);
    float d =     fmaf(w, fmaf(w, fmaf(w, 1.0f, 210.0f), 4725.0f), 10395.0f);
    return __fdividef(n, d);
}

__global__ void __launch_bounds__(128, 5) qlstm_kernel(
    const float* __restrict__ inp,   // [T, B, 4]
    const float* __restrict__ prm_f, // [8]
    const float* __restrict__ prm_i,
    const float* __restrict__ prm_g,
    const float* __restrict__ prm_o,
    float* __restrict__ out)         // [T*B*4 + B*4 + B*4]
{
    const int wid   = threadIdx.x >> 5;      // 0..3
    const int lane  = threadIdx.x & 31;
    const int half  = wid & 1;               // t-half: 0 -> t<64, 1 -> t>=64
    const int pair  = wid >> 1;              // b-pair within block
    const int bsub  = lane & 1;
    const int chunk = lane >> 1;             // 0..15
    const int b     = blockIdx.x * 4 + pair * 2 + bsub;
    const int t0    = half * 64 + chunk * CHUNK;

    // smem link: half-0's total c at t=63, per (pair, bsub, k)
    __shared__ float sC[2][2][4];

    // per-k parameter prefix products (uniform)
    float AFh[4], AIh[4], AG[4], AOh[4];
    {
        float pf_ = 1.0f, pi_ = 1.0f, pg_ = 1.0f, po_ = 1.0f;
#pragma unroll
        for (int j = 0; j < 4; ++j) {
            pf_ *= __cosf(prm_f[j]);
            pi_ *= __cosf(prm_i[j]);
            pg_ *= __cosf(prm_g[j]);
            po_ *= __cosf(prm_o[j]);
            AFh[j] = 0.5f * pf_;   // sigmoid poly takes arg/2
            AIh[j] = 0.5f * pi_;
            AG[j]  = pg_;
            AOh[j] = 0.5f * po_;
        }
    }

    const float4* __restrict__ xin = (const float4*)inp;

    // ---- pass 1: load once, cache gates, accumulate chunk affine map ----
    float Fc[CHUNK][4], Gc[CHUNK][4], Oc[CHUNK][4];
    float cl0 = 0.f, cl1 = 0.f, cl2 = 0.f, cl3 = 0.f;
    float pf0 = 1.f, pf1 = 1.f, pf2 = 1.f, pf3 = 1.f;

#pragma unroll
    for (int it = 0; it < CHUNK; ++it) {
        float4 x = xin[(t0 + it) * BATCH + b];
        float P0 = __cosf(x.x);
        float P1 = P0 * __cosf(x.y);
        float P2 = P1 * __cosf(x.z);
        float P3 = P2 * __cosf(x.w);

        float f, i, g, ig;
        f = sig_poly(AFh[0] * P0); i = sig_poly(AIh[0] * P0); g = tanh_p54(AG[0] * P0);
        ig = i * g; Fc[it][0] = f; Gc[it][0] = ig; Oc[it][0] = sig_poly(AOh[0] * P0);
        cl0 = fmaf(f, cl0, ig); pf0 *= f;

        f = sig_poly(AFh[1] * P1); i = sig_poly(AIh[1] * P1); g = tanh_p54(AG[1] * P1);
        ig = i * g; Fc[it][1] = f; Gc[it][1] = ig; Oc[it][1] = sig_poly(AOh[1] * P1);
        cl1 = fmaf(f, cl1, ig); pf1 *= f;

        f = sig_poly(AFh[2] * P2); i = sig_poly(AIh[2] * P2); g = tanh_p54(AG[2] * P2);
        ig = i * g; Fc[it][2] = f; Gc[it][2] = ig; Oc[it][2] = sig_poly(AOh[2] * P2);
        cl2 = fmaf(f, cl2, ig); pf2 *= f;

        f = sig_poly(AFh[3] * P3); i = sig_poly(AIh[3] * P3); g = tanh_p54(AG[3] * P3);
        ig = i * g; Fc[it][3] = f; Gc[it][3] = ig; Oc[it][3] = sig_poly(AOh[3] * P3);
        cl3 = fmaf(f, cl3, ig); pf3 *= f;
    }

    // ---- scan over 16 chunks (lanes stride 2, same bsub) ----
    float F0 = pf0, C0 = cl0, F1 = pf1, C1 = cl1;
    float F2 = pf2, C2 = cl2, F3 = pf3, C3 = cl3;
#pragma unroll
    for (int off = 1; off <= 8; off <<= 1) {
        const int ol = off * 2;
        float Fo0 = __shfl_up_sync(FULLMASK, F0, ol), Co0 = __shfl_up_sync(FULLMASK, C0, ol);
        float Fo1 = __shfl_up_sync(FULLMASK, F1, ol), Co1 = __shfl_up_sync(FULLMASK, C1, ol);
        float Fo2 = __shfl_up_sync(FULLMASK, F2, ol), Co2 = __shfl_up_sync(FULLMASK, C2, ol);
        float Fo3 = __shfl_up_sync(FULLMASK, F3, ol), Co3 = __shfl_up_sync(FULLMASK, C3, ol);
        if (chunk >= off) {
            C0 = fmaf(F0, Co0, C0); F0 *= Fo0;
            C1 = fmaf(F1, Co1, C1); F1 *= Fo1;
            C2 = fmaf(F2, Co2, C2); F2 *= Fo2;
            C3 = fmaf(F3, Co3, C3); F3 *= Fo3;
        }
    }

    // half-0 publishes total c at t=63 (chunk 15 inclusive, c_in = 0)
    if (half == 0 && chunk == 15) {
        sC[pair][bsub][0] = C0;
        sC[pair][bsub][1] = C1;
        sC[pair][bsub][2] = C2;
        sC[pair][bsub][3] = C3;
    }

    // exclusive prefix within this half
    float Fe0 = __shfl_up_sync(FULLMASK, F0, 2), Ce0 = __shfl_up_sync(FULLMASK, C0, 2);
    float Fe1 = __shfl_up_sync(FULLMASK, F1, 2), Ce1 = __shfl_up_sync(FULLMASK, C1, 2);
    float Fe2 = __shfl_up_sync(FULLMASK, F2, 2), Ce2 = __shfl_up_sync(FULLMASK, C2, 2);
    float Fe3 = __shfl_up_sync(FULLMASK, F3, 2), Ce3 = __shfl_up_sync(FULLMASK, C3, 2);
    if (chunk == 0) {
        Fe0 = 1.f; Ce0 = 0.f; Fe1 = 1.f; Ce1 = 0.f;
        Fe2 = 1.f; Ce2 = 0.f; Fe3 = 1.f; Ce3 = 0.f;
    }

    __syncthreads();

    // incoming c for this half (0 for half 0; half-0's total for half 1)
    float ch0 = 0.f, ch1 = 0.f, ch2 = 0.f, ch3 = 0.f;
    if (half == 1) {
        ch0 = sC[pair][bsub][0];
        ch1 = sC[pair][bsub][1];
        ch2 = sC[pair][bsub][2];
        ch3 = sC[pair][bsub][3];
    }

    float c0 = fmaf(Fe0, ch0, Ce0);
    float c1 = fmaf(Fe1, ch1, Ce1);
    float c2 = fmaf(Fe2, ch2, Ce2);
    float c3 = fmaf(Fe3, ch3, Ce3);

    // ---- pass 2: pure-register recurrence, emit h ----
    float4* __restrict__ out4 = (float4*)out;
    float h0 = 0.f, h1 = 0.f, h2 = 0.f, h3 = 0.f;

#pragma unroll
    for (int it = 0; it < CHUNK; ++it) {
        c0 = fmaf(Fc[it][0], c0, Gc[it][0]);
        c1 = fmaf(Fc[it][1], c1, Gc[it][1]);
        c2 = fmaf(Fc[it][2], c2, Gc[it][2]);
        c3 = fmaf(Fc[it][3], c3, Gc[it][3]);

        h0 = Oc[it][0] * tanh_p76(c0);
        h1 = Oc[it][1] * tanh_p76(c1);
        h2 = Oc[it][2] * tanh_p76(c2);
        h3 = Oc[it][3] * tanh_p76(c3);

        __stcs(&out4[(t0 + it) * BATCH + b], make_float4(h0, h1, h2, h3));
    }

    // final state from half 1, chunk 15, it=3 (t = 127)
    if (half == 1 && chunk == 15) {
        out4[T_STEPS * BATCH + b]         = make_float4(h0, h1, h2, h3); // hx
        out4[T_STEPS * BATCH + BATCH + b] = make_float4(c0, c1, c2, c3); // cx
    }
}

extern "C" void kernel_launch(void* const* d_in, const int* in_sizes, int n_in,
                              void* d_out, int out_size) {
    (void)in_sizes; (void)n_in; (void)out_size;
    const float* inp   = (const float*)d_in[0];
    const float* prm_f = (const float*)d_in[1];
    const float* prm_i = (const float*)d_in[2];
    const float* prm_g = (const float*)d_in[3];
    const float* prm_o = (const float*)d_in[4];
    float* out = (float*)d_out;

    // 4096 warps: 2 b x half-T per warp; 4 warps/block -> 1024 blocks
    qlstm_kernel<<<1024, 128>>>(inp, prm_f, prm_i, prm_g, prm_o, out);
}